// round 1
// baseline (speedup 1.0000x reference)
#include <cuda_runtime.h>
#include <math.h>

#define BB 64
#define SS 512
#define DD 512
#define HH 1024
#define GG 4096   // 4*HH

// Scratch (device-global: no allocations allowed in kernel_launch).
__device__ float g_gx[(size_t)BB * SS * GG];   // (B*S, 4H) input projections, 512MB
__device__ float g_c[BB * HH];                 // cell state

// ---------------------------------------------------------------------------
// Kernel 1: gx[m, n] = sum_k x[m, k] * Wx[n, k] + (bx[n] + bh[n])
//   M = B*S = 32768, N = 4096, K = 512. Both operands K-major.
//   64x64 tile, BK=16, 256 threads, 4x4 register tile, float4 smem reads.
// ---------------------------------------------------------------------------
__global__ __launch_bounds__(256) void gx_gemm(const float* __restrict__ x,
                                               const float* __restrict__ Wx,
                                               const float* __restrict__ bx,
                                               const float* __restrict__ bh) {
    __shared__ float As[16][64];   // [k][m]
    __shared__ float Ws[16][64];   // [k][n]

    const int tid = threadIdx.x;
    const int tx  = tid & 15;      // n-group
    const int ty  = tid >> 4;      // m-group
    const int m0  = blockIdx.y * 64;
    const int n0  = blockIdx.x * 64;

    const int lrow = tid >> 2;         // 0..63 (row within tile)
    const int lk   = (tid & 3) << 2;   // 0,4,8,12 (k within k-tile)

    float acc[4][4];
#pragma unroll
    for (int i = 0; i < 4; i++)
#pragma unroll
        for (int j = 0; j < 4; j++) acc[i][j] = 0.f;

    const float* aptr = x  + (size_t)(m0 + lrow) * DD + lk;
    const float* wptr = Wx + (size_t)(n0 + lrow) * DD + lk;

    for (int kt = 0; kt < DD; kt += 16) {
        float4 av = *(const float4*)(aptr + kt);
        float4 wv = *(const float4*)(wptr + kt);
        __syncthreads();
        As[lk + 0][lrow] = av.x; As[lk + 1][lrow] = av.y;
        As[lk + 2][lrow] = av.z; As[lk + 3][lrow] = av.w;
        Ws[lk + 0][lrow] = wv.x; Ws[lk + 1][lrow] = wv.y;
        Ws[lk + 2][lrow] = wv.z; Ws[lk + 3][lrow] = wv.w;
        __syncthreads();
#pragma unroll
        for (int kk = 0; kk < 16; kk++) {
            float4 a4 = *(const float4*)&As[kk][ty * 4];
            float4 b4 = *(const float4*)&Ws[kk][tx * 4];
            float a[4] = {a4.x, a4.y, a4.z, a4.w};
            float b[4] = {b4.x, b4.y, b4.z, b4.w};
#pragma unroll
            for (int i = 0; i < 4; i++)
#pragma unroll
                for (int j = 0; j < 4; j++)
                    acc[i][j] = fmaf(a[i], b[j], acc[i][j]);
        }
    }

    // Epilogue: add fused bias, store float4 along n.
    const int nb = n0 + tx * 4;
    float4 bias;
    bias.x = bx[nb + 0] + bh[nb + 0];
    bias.y = bx[nb + 1] + bh[nb + 1];
    bias.z = bx[nb + 2] + bh[nb + 2];
    bias.w = bx[nb + 3] + bh[nb + 3];
#pragma unroll
    for (int i = 0; i < 4; i++) {
        const size_t m = (size_t)(m0 + ty * 4 + i);
        float4 v;
        v.x = acc[i][0] + bias.x;
        v.y = acc[i][1] + bias.y;
        v.z = acc[i][2] + bias.z;
        v.w = acc[i][3] + bias.w;
        *(float4*)&g_gx[m * GG + nb] = v;
    }
}

// ---------------------------------------------------------------------------
// Kernel 2: one LSTM timestep.
//   gates[b, g*H + j] = gx[b, t, g*H + j] + sum_k h_{t-1}[b, k] * Wh[g*H + j, k]
//   Grid: 128 CTAs, each owns 8 h-columns (j0..j0+7) x all 4 gates x all 64 b.
//   256 threads: thread = (batch-pair tg, column tx); register tile 2b x 4gates.
//   k-tile 32, float4 (k-packed) smem reads, padded stride 36 (conflict-free).
//   h_{t-1} is read from the output buffer (row t-1). c state in g_c.
// ---------------------------------------------------------------------------
__global__ __launch_bounds__(256) void lstm_step(const float* __restrict__ Wh,
                                                 float* __restrict__ out,
                                                 int t, int write_final) {
    __shared__ float Hs[64][36];   // h[b][k] tile, padded
    __shared__ float Wsm[32][36];  // Wh rows for this CTA: lr = g*8 + jloc

    const int tid = threadIdx.x;
    const int tx  = tid & 7;       // column within tile
    const int tg  = tid >> 3;      // 0..31 batch-pair
    const int b0  = tg * 2;
    const int j0  = blockIdx.x * 8;
    const int j   = j0 + tx;

    float acc[2][4];
#pragma unroll
    for (int r = 0; r < 2; r++)
#pragma unroll
        for (int g = 0; g < 4; g++) acc[r][g] = 0.f;

    if (t > 0) {
        for (int kt = 0; kt < HH; kt += 32) {
            __syncthreads();
            // Load h tile: 64 b x 32 k = 512 float4s, 2 per thread.
#pragma unroll
            for (int r = 0; r < 2; r++) {
                int idx = tid + r * 256;
                int b   = idx >> 3;
                int k4  = (idx & 7) << 2;
                float4 v = *(const float4*)(out + ((size_t)b * SS + (t - 1)) * HH + kt + k4);
                *(float4*)&Hs[b][k4] = v;
            }
            // Load Wh tile: 32 rows x 32 k = 256 float4s, 1 per thread.
            {
                int lr = tid >> 3;             // 0..31
                int k4 = (tid & 7) << 2;
                int g  = lr >> 3;
                int jl = lr & 7;
                float4 v = *(const float4*)(Wh + (size_t)(g * HH + j0 + jl) * HH + kt + k4);
                *(float4*)&Wsm[lr][k4] = v;
            }
            __syncthreads();
#pragma unroll
            for (int kk = 0; kk < 32; kk += 4) {
                float4 h0 = *(const float4*)&Hs[b0][kk];
                float4 h1 = *(const float4*)&Hs[b0 + 1][kk];
#pragma unroll
                for (int g = 0; g < 4; g++) {
                    float4 w = *(const float4*)&Wsm[g * 8 + tx][kk];
                    acc[0][g] = fmaf(h0.x, w.x, acc[0][g]);
                    acc[0][g] = fmaf(h0.y, w.y, acc[0][g]);
                    acc[0][g] = fmaf(h0.z, w.z, acc[0][g]);
                    acc[0][g] = fmaf(h0.w, w.w, acc[0][g]);
                    acc[1][g] = fmaf(h1.x, w.x, acc[1][g]);
                    acc[1][g] = fmaf(h1.y, w.y, acc[1][g]);
                    acc[1][g] = fmaf(h1.z, w.z, acc[1][g]);
                    acc[1][g] = fmaf(h1.w, w.w, acc[1][g]);
                }
            }
        }
    }

    // Epilogue: gate activations + state update.
#pragma unroll
    for (int r = 0; r < 2; r++) {
        const int b = b0 + r;
        const size_t gbase = ((size_t)b * SS + t) * (size_t)GG + j;
        float iv = acc[r][0] + g_gx[gbase + 0 * HH];
        float fv = acc[r][1] + g_gx[gbase + 1 * HH];
        float gv = acc[r][2] + g_gx[gbase + 2 * HH];
        float ov = acc[r][3] + g_gx[gbase + 3 * HH];
        iv = 1.f / (1.f + expf(-iv));
        fv = 1.f / (1.f + expf(-fv));
        gv = tanhf(gv);
        ov = 1.f / (1.f + expf(-ov));
        const float cp = (t > 0) ? g_c[b * HH + j] : 0.f;
        const float cn = fmaf(fv, cp, iv * gv);
        const float hn = ov * tanhf(cn);
        g_c[b * HH + j] = cn;
        out[((size_t)b * SS + t) * HH + j] = hn;
        if (write_final && t == SS - 1) {
            // leaves: hidden_state, h_T, c_T
            out[(size_t)BB * SS * HH + (size_t)b * HH + j] = hn;
            out[(size_t)BB * SS * HH + (size_t)BB * HH + (size_t)b * HH + j] = cn;
        }
    }
}

// ---------------------------------------------------------------------------
extern "C" void kernel_launch(void* const* d_in, const int* in_sizes, int n_in,
                              void* d_out, int out_size) {
    const float* x  = (const float*)d_in[0];
    const float* Wx = (const float*)d_in[1];
    const float* Wh = (const float*)d_in[2];
    const float* bx = (const float*)d_in[3];
    const float* bh = (const float*)d_in[4];
    float* out = (float*)d_out;

    const long long full = (long long)BB * SS * HH + 2LL * BB * HH;
    const int write_final = ((long long)out_size >= full) ? 1 : 0;

    // 1) Input projections for all timesteps (one big GEMM, biases folded).
    gx_gemm<<<dim3(GG / 64, (BB * SS) / 64), 256>>>(x, Wx, bx, bh);

    // 2) Sequential scan: 512 dependent step kernels in the graph.
    for (int t = 0; t < SS; t++) {
        lstm_step<<<HH / 8, 256>>>(Wh, out, t, write_final);
    }
}